// round 9
// baseline (speedup 1.0000x reference)
#include <cuda_runtime.h>
#include <cuda_bf16.h>
#include <cstdint>

#define H 128
#define NMAX 100000
#define EMAX 1600000
#define NG 512
#define SCANB 1024

// ---- scratch (static __device__ globals; no allocation allowed) ----
__device__ __align__(256) __nv_bfloat16 g_hA[(size_t)NMAX * H];
__device__ __align__(256) __nv_bfloat16 g_hB[(size_t)NMAX * H];
__device__ __align__(256) __nv_bfloat16 g_t[(size_t)NMAX * H];
__device__ int   g_count[NMAX];
__device__ int   g_fill[NMAX];
__device__ int   g_rowptr[NMAX + 1];
__device__ int   g_src[EMAX];
__device__ int   g_gptr[NG + 1];
__device__ int   g_bsum[128];
__device__ int   g_boff[128];
__device__ float g_p[NG * 5 * H];
__device__ float g_q[NG * 5 * H];
// pre-split, pre-swizzled bf16 W images: 32KB per (layer, hi/lo)
__device__ __align__(16) unsigned char g_whi[4][32768];
__device__ __align__(16) unsigned char g_wlo[4][32768];

__device__ __forceinline__ uint32_t smem_u32(const void* p) {
    uint32_t a;
    asm("{ .reg .u64 t; cvta.to.shared.u64 t, %1; cvt.u32.u64 %0, t; }" : "=r"(a) : "l"(p));
    return a;
}

#define LDSM_X4(r, addr) \
    asm volatile("ldmatrix.sync.aligned.m8n8.x4.shared.b16 {%0,%1,%2,%3}, [%4];" \
        : "=r"((r)[0]), "=r"((r)[1]), "=r"((r)[2]), "=r"((r)[3]) : "r"(addr))
#define LDSM_X4_T(r, addr) \
    asm volatile("ldmatrix.sync.aligned.m8n8.x4.trans.shared.b16 {%0,%1,%2,%3}, [%4];" \
        : "=r"((r)[0]), "=r"((r)[1]), "=r"((r)[2]), "=r"((r)[3]) : "r"(addr))
#define MMA_BF16(c, a, b0, b1) \
    asm volatile("mma.sync.aligned.m16n8k16.row.col.f32.bf16.bf16.f32 " \
        "{%0,%1,%2,%3}, {%4,%5,%6,%7}, {%8,%9}, {%0,%1,%2,%3};" \
        : "+f"((c)[0]), "+f"((c)[1]), "+f"((c)[2]), "+f"((c)[3]) \
        : "r"((a)[0]), "r"((a)[1]), "r"((a)[2]), "r"((a)[3]), "r"(b0), "r"(b1))

// 256B-row XOR swizzle: chunk[4:6] ^= row[0:2]  (rows at 256B stride)
#define SWZ(off) ((uint32_t)(off) ^ (((uint32_t)(off) >> 4) & 0x70))

__device__ __forceinline__ uint32_t pack2(float a, float b) {
    uint32_t lo = __bfloat16_as_ushort(__float2bfloat16_rn(a));
    uint32_t hi = __bfloat16_as_ushort(__float2bfloat16_rn(b));
    return lo | (hi << 16);
}

__device__ __forceinline__ float2 b2f(uint32_t u) {
    __nv_bfloat162 h = *reinterpret_cast<__nv_bfloat162*>(&u);
    return __bfloat1622float2(h);
}

// split 8 fp32 (two float4) into 16B hi + 16B lo bf16 images
__device__ __forceinline__ void split8(float4 v0, float4 v1, uint4& hp, uint4& lp) {
    __nv_bfloat16 h0 = __float2bfloat16_rn(v0.x), h1 = __float2bfloat16_rn(v0.y);
    __nv_bfloat16 h2 = __float2bfloat16_rn(v0.z), h3 = __float2bfloat16_rn(v0.w);
    __nv_bfloat16 h4 = __float2bfloat16_rn(v1.x), h5 = __float2bfloat16_rn(v1.y);
    __nv_bfloat16 h6 = __float2bfloat16_rn(v1.z), h7 = __float2bfloat16_rn(v1.w);
    hp.x = (uint32_t)__bfloat16_as_ushort(h0) | ((uint32_t)__bfloat16_as_ushort(h1) << 16);
    hp.y = (uint32_t)__bfloat16_as_ushort(h2) | ((uint32_t)__bfloat16_as_ushort(h3) << 16);
    hp.z = (uint32_t)__bfloat16_as_ushort(h4) | ((uint32_t)__bfloat16_as_ushort(h5) << 16);
    hp.w = (uint32_t)__bfloat16_as_ushort(h6) | ((uint32_t)__bfloat16_as_ushort(h7) << 16);
    lp.x = pack2(v0.x - __bfloat162float(h0), v0.y - __bfloat162float(h1));
    lp.y = pack2(v0.z - __bfloat162float(h2), v0.w - __bfloat162float(h3));
    lp.z = pack2(v1.x - __bfloat162float(h4), v1.y - __bfloat162float(h5));
    lp.w = pack2(v1.z - __bfloat162float(h6), v1.w - __bfloat162float(h7));
}

// ---- W prep: fp32 [128][128] -> pre-swizzled bf16 hi/lo images (per layer) ----
__global__ void k_wprep(const float* __restrict__ W0, const float* __restrict__ W1,
                        const float* __restrict__ W2, const float* __restrict__ W3) {
    const float* Ws[4] = {W0, W1, W2, W3};
    int layer = blockIdx.y;
    int idx = blockIdx.x * blockDim.x + threadIdx.x;   // 0..2047 = k*16 + chunk
    int k = idx >> 4, c = idx & 15;
    const float* W = Ws[layer];
    float4 v0 = *(const float4*)&W[(size_t)k * H + c * 8];
    float4 v1 = *(const float4*)&W[(size_t)k * H + c * 8 + 4];
    uint4 hp, lp;
    split8(v0, v1, hp, lp);
    uint32_t off = SWZ(k * 256 + c * 16);
    *(uint4*)&g_whi[layer][off] = hp;
    *(uint4*)&g_wlo[layer][off] = lp;
}

// ---- preprocessing (init + convert x -> bf16 fused) ----
__global__ void k_init_cvt(const float* __restrict__ x, __nv_bfloat16* __restrict__ o, int n) {
    int i = blockIdx.x * blockDim.x + threadIdx.x;
    if (i < n) { g_count[i] = 0; g_fill[i] = 0; }
    if (i <= NG) g_gptr[i] = n;
    int total4 = n * 32;                  // float4 chunks of x
    if (i < total4) {
        float4 v = ((const float4*)x)[i];
        uint2 p;
        p.x = pack2(v.x, v.y);
        p.y = pack2(v.z, v.w);
        ((uint2*)o)[i] = p;
    }
}

__global__ void k_hist(const int* __restrict__ col, int E) {
    int i = blockIdx.x * blockDim.x + threadIdx.x;
    if (i < E) atomicAdd(&g_count[col[i]], 1);
}

__global__ __launch_bounds__(SCANB) void k_scan1(int n) {
    __shared__ int warpsum[32];
    int gid = blockIdx.x * SCANB + threadIdx.x;
    int lane = threadIdx.x & 31, wid = threadIdx.x >> 5;
    int v = (gid < n) ? g_count[gid] : 0;
    int x = v;
#pragma unroll
    for (int d = 1; d < 32; d <<= 1) {
        int t = __shfl_up_sync(0xffffffffu, x, d);
        if (lane >= d) x += t;
    }
    if (lane == 31) warpsum[wid] = x;
    __syncthreads();
    if (wid == 0) {
        int s = warpsum[lane];
#pragma unroll
        for (int d = 1; d < 32; d <<= 1) {
            int t = __shfl_up_sync(0xffffffffu, s, d);
            if (lane >= d) s += t;
        }
        warpsum[lane] = s;
    }
    __syncthreads();
    int excl = x - v + (wid > 0 ? warpsum[wid - 1] : 0);
    if (gid < n) g_rowptr[gid] = excl;
    if (threadIdx.x == SCANB - 1) g_bsum[blockIdx.x] = warpsum[31];
}

__global__ void k_scan2(int nb, int n) {
    __shared__ int warpsum[4];
    int tid = threadIdx.x;
    int lane = tid & 31, wid = tid >> 5;
    int v = (tid < nb) ? g_bsum[tid] : 0;
    int x = v;
#pragma unroll
    for (int d = 1; d < 32; d <<= 1) {
        int t = __shfl_up_sync(0xffffffffu, x, d);
        if (lane >= d) x += t;
    }
    if (lane == 31) warpsum[wid] = x;
    __syncthreads();
    int base = 0;
    for (int w = 0; w < wid; ++w) base += warpsum[w];
    g_boff[tid] = base + x - v;
    if (tid == 127) g_rowptr[n] = base + x;
}

__global__ __launch_bounds__(SCANB) void k_scan3(int n) {
    int gid = blockIdx.x * SCANB + threadIdx.x;
    if (gid < n) g_rowptr[gid] += g_boff[blockIdx.x];
}

__global__ void k_scatter(const int* __restrict__ row, const int* __restrict__ col, int E) {
    int i = blockIdx.x * blockDim.x + threadIdx.x;
    if (i < E) {
        int c = col[i];
        int pos = g_rowptr[c] + atomicAdd(&g_fill[c], 1);
        g_src[pos] = row[i];
    }
}

__global__ void k_gmin(const int* __restrict__ batch, int n) {
    int i = blockIdx.x * blockDim.x + threadIdx.x;
    if (i < n) atomicMin(&g_gptr[batch[i]], i);
}

// parallel suffix-min over g_gptr[0..NG-1] with sentinel g_gptr[NG]=n
__global__ __launch_bounds__(NG) void k_gfix() {
    __shared__ int sm[NG + 1];
    int tid = threadIdx.x;
    sm[tid] = g_gptr[tid];
    if (tid == 0) sm[NG] = g_gptr[NG];
    __syncthreads();
    for (int d = 1; d <= NG; d <<= 1) {
        int v = (tid + d <= NG) ? sm[tid + d] : 0x7fffffff;
        __syncthreads();
        if (v < sm[tid]) sm[tid] = v;
        __syncthreads();
    }
    g_gptr[tid] = sm[tid];
}

// ---- HMMA GEMM: t[m,:] = bf16(dinv[m] * (A[m,:] @ W)), A bf16, W pre-split ----
// CTA tile 128x128, 8 warps (4x2 grid, warp tile 32x64); XOR-swizzled smem:
//   A 32KB, W hi/lo 32KB each = 96KB -> 2 CTAs/SM
#define SA     0
#define SW_HI  32768
#define SW_LO  65536
#define SM_TOTAL 98304

__global__ __launch_bounds__(256, 2) void k_gemm_mma(const __nv_bfloat16* __restrict__ A,
                                                     const unsigned char* __restrict__ Whi,
                                                     const unsigned char* __restrict__ Wlo,
                                                     __nv_bfloat16* __restrict__ C, int nrows) {
    extern __shared__ char smem[];
    uint32_t sb = smem_u32(smem);
    int tid = threadIdx.x, lane = tid & 31, wid = tid >> 5;
    int wm = wid >> 1, wn = wid & 1;      // 4x2 warp grid; warp tile 32x64
    int m0 = blockIdx.x * 128;

    // prologue: copy pre-swizzled W images (straight byte copy)
    {
        const uint4* __restrict__ s1 = (const uint4*)Whi;
        const uint4* __restrict__ s2 = (const uint4*)Wlo;
        uint4* d1 = (uint4*)(smem + SW_HI);
        uint4* d2 = (uint4*)(smem + SW_LO);
#pragma unroll
        for (int j = 0; j < 8; ++j) {
            int i = j * 256 + tid;
            d1[i] = s1[i];
            d2[i] = s2[i];
        }
    }
    // prologue A: 128 rows x 256B bf16, straight copy with swizzle
#pragma unroll
    for (int j = 0; j < 8; ++j) {
        int idx = j * 256 + tid;          // 2048 items: r*16 + chunk
        int r = idx >> 4, c = idx & 15;
        int m = m0 + r;
        uint4 v = make_uint4(0u, 0u, 0u, 0u);
        if (m < nrows) v = *(const uint4*)&A[(size_t)m * H + c * 8];
        *(uint4*)(smem + SA + SWZ(r * 256 + c * 16)) = v;
    }
    __syncthreads();

    float c[2][8][4];
#pragma unroll
    for (int mi = 0; mi < 2; ++mi)
#pragma unroll
        for (int nj = 0; nj < 8; ++nj)
#pragma unroll
            for (int q = 0; q < 4; ++q) c[mi][nj][q] = 0.f;

    int arow_lo = lane & 15;
    int asel = lane >> 4;

#pragma unroll
    for (int kc = 0; kc < 8; ++kc) {
        uint32_t a[2][4], bhi[4][4], blo[4][4];
#pragma unroll
        for (int mi = 0; mi < 2; ++mi) {
            int row = wm * 32 + mi * 16 + arow_lo;
            LDSM_X4(a[mi], sb + SA + SWZ(row * 256 + (kc * 2 + asel) * 16));
        }
        int krow = kc * 16 + arow_lo;
#pragma unroll
        for (int ni = 0; ni < 4; ++ni)
            LDSM_X4_T(bhi[ni], sb + SW_HI + SWZ(krow * 256 + (wn * 8 + ni * 2 + asel) * 16));
        // product 1: A x Whi  (16 distinct accumulators -> no RAW chain)
#pragma unroll
        for (int mi = 0; mi < 2; ++mi)
#pragma unroll
            for (int ni = 0; ni < 4; ++ni) {
                MMA_BF16(c[mi][2 * ni],     a[mi], bhi[ni][0], bhi[ni][1]);
                MMA_BF16(c[mi][2 * ni + 1], a[mi], bhi[ni][2], bhi[ni][3]);
            }
#pragma unroll
        for (int ni = 0; ni < 4; ++ni)
            LDSM_X4_T(blo[ni], sb + SW_LO + SWZ(krow * 256 + (wn * 8 + ni * 2 + asel) * 16));
        // product 2: A x Wlo
#pragma unroll
        for (int mi = 0; mi < 2; ++mi)
#pragma unroll
            for (int ni = 0; ni < 4; ++ni) {
                MMA_BF16(c[mi][2 * ni],     a[mi], blo[ni][0], blo[ni][1]);
                MMA_BF16(c[mi][2 * ni + 1], a[mi], blo[ni][2], blo[ni][3]);
            }
    }

    // epilogue: scale by dinv (inline rsqrt of degree), convert to bf16, store
#pragma unroll
    for (int mi = 0; mi < 2; ++mi) {
        int r = m0 + wm * 32 + mi * 16 + (lane >> 2);
        int r8 = r + 8;
        float d0 = (r < nrows) ? rsqrtf((float)(g_count[r] + 1)) : 0.f;
        float d8 = (r8 < nrows) ? rsqrtf((float)(g_count[r8] + 1)) : 0.f;
#pragma unroll
        for (int nj = 0; nj < 8; ++nj) {
            int col = wn * 64 + nj * 8 + (lane & 3) * 2;
            if (r < nrows)
                *(uint32_t*)&C[(size_t)r * H + col] = pack2(d0 * c[mi][nj][0], d0 * c[mi][nj][1]);
            if (r8 < nrows)
                *(uint32_t*)&C[(size_t)r8 * H + col] = pack2(d8 * c[mi][nj][2], d8 * c[mi][nj][3]);
        }
    }
}

// ---- SpMM: h[i] = bf16(relu(dinv[i]*(t[i] + sum_src t[src]) + b)), t bf16 ----
// 1 warp per node; lane covers 4 cols (uint2 = 4 bf16)
__global__ __launch_bounds__(256) void k_spmm(const __nv_bfloat16* __restrict__ t,
                                              const float* __restrict__ bias,
                                              __nv_bfloat16* __restrict__ h, int n) {
    int node = (blockIdx.x * blockDim.x + threadIdx.x) >> 5;
    if (node >= n) return;
    int lane = threadIdx.x & 31;
    const uint2* __restrict__ t2 = (const uint2*)t;   // row = 32 uint2

    int e0 = g_rowptr[node], e1 = g_rowptr[node + 1];
    float di = rsqrtf((float)(e1 - e0 + 1));
    uint2 sv = t2[(size_t)node * 32 + lane];
    float2 s0 = b2f(sv.x), s1 = b2f(sv.y);
    float ax = s0.x, ay = s0.y, az = s1.x, aw = s1.y;
    float bx = 0.f, by = 0.f, bz = 0.f, bw = 0.f;
    float cx = 0.f, cy = 0.f, cz = 0.f, cw = 0.f;
    float dx = 0.f, dy = 0.f, dz = 0.f, dw = 0.f;
    int e = e0;
    for (; e + 3 < e1; e += 4) {
        int i0 = g_src[e], i1 = g_src[e + 1], i2 = g_src[e + 2], i3 = g_src[e + 3];
        uint2 v0 = t2[(size_t)i0 * 32 + lane];
        uint2 v1 = t2[(size_t)i1 * 32 + lane];
        uint2 v2 = t2[(size_t)i2 * 32 + lane];
        uint2 v3 = t2[(size_t)i3 * 32 + lane];
        float2 p;
        p = b2f(v0.x); ax += p.x; ay += p.y;  p = b2f(v0.y); az += p.x; aw += p.y;
        p = b2f(v1.x); bx += p.x; by += p.y;  p = b2f(v1.y); bz += p.x; bw += p.y;
        p = b2f(v2.x); cx += p.x; cy += p.y;  p = b2f(v2.y); cz += p.x; cw += p.y;
        p = b2f(v3.x); dx += p.x; dy += p.y;  p = b2f(v3.y); dz += p.x; dw += p.y;
    }
    for (; e < e1; ++e) {
        int s = g_src[e];
        uint2 v = t2[(size_t)s * 32 + lane];
        float2 p;
        p = b2f(v.x); ax += p.x; ay += p.y;
        p = b2f(v.y); az += p.x; aw += p.y;
    }
    float4 bi = ((const float4*)bias)[lane];
    float r0 = fmaxf(fmaf(di, (ax + bx) + (cx + dx), bi.x), 0.f);
    float r1 = fmaxf(fmaf(di, (ay + by) + (cy + dy), bi.y), 0.f);
    float r2 = fmaxf(fmaf(di, (az + bz) + (cz + dz), bi.z), 0.f);
    float r3 = fmaxf(fmaf(di, (aw + bw) + (cw + dw), bi.w), 0.f);
    uint2 o;
    o.x = pack2(r0, r1);
    o.y = pack2(r2, r3);
    ((uint2*)h)[(size_t)node * 32 + lane] = o;
}

// ---- global mean pool (h bf16) ----
__global__ void k_pool(const __nv_bfloat16* __restrict__ h, int off) {
    int g = blockIdx.x, tx = threadIdx.x;
    int s = g_gptr[g], e = g_gptr[g + 1];
    float sum = 0.f;
    for (int i = s; i < e; ++i) sum += __bfloat162float(h[(size_t)i * H + tx]);
    int cnt = e - s;
    g_p[g * (5 * H) + off + tx] = sum / (float)(cnt > 0 ? cnt : 1);
}

// ---- MLP head ----
__global__ void k_mlp1(const float* __restrict__ Wl1, const float* __restrict__ bl1) {
    __shared__ float ps[5 * H];
    int g = blockIdx.y;
    int j = blockIdx.x * H + threadIdx.x;
    for (int k = threadIdx.x; k < 5 * H; k += H) ps[k] = g_p[g * (5 * H) + k];
    __syncthreads();
    float acc = bl1[j];
    for (int k = 0; k < 5 * H; ++k) acc = fmaf(ps[k], Wl1[(size_t)k * (5 * H) + j], acc);
    g_q[g * (5 * H) + j] = fmaxf(acc, 0.f);
}

__global__ void k_mlp2(const float* __restrict__ Wl2, const float* __restrict__ bl2,
                       float* __restrict__ out) {
    __shared__ float red[H];
    int g = blockIdx.x, tid = threadIdx.x;
    float s = 0.f;
    for (int k = tid; k < 5 * H; k += H) s = fmaf(g_q[g * (5 * H) + k], Wl2[k], s);
    red[tid] = s;
    __syncthreads();
    for (int d = H / 2; d > 0; d >>= 1) {
        if (tid < d) red[tid] += red[tid + d];
        __syncthreads();
    }
    if (tid == 0) out[g] = red[0] + bl2[0];
}

// ---- launch ----
extern "C" void kernel_launch(void* const* d_in, const int* in_sizes, int n_in,
                              void* d_out, int out_size) {
    const float* x     = (const float*)d_in[0];
    const int*   edge  = (const int*)d_in[1];
    const int*   batch = (const int*)d_in[2];
    const float* B[5]  = {(const float*)d_in[4], (const float*)d_in[6],
                          (const float*)d_in[8], (const float*)d_in[10],
                          (const float*)d_in[10]};  // layer 5 reuses b4
    const float* Wl1 = (const float*)d_in[11];
    const float* bl1 = (const float*)d_in[12];
    const float* Wl2 = (const float*)d_in[13];
    const float* bl2 = (const float*)d_in[14];
    float* out = (float*)d_out;

    int n = in_sizes[0] / H;
    int E = in_sizes[1] / 2;
    const int* row = edge;       // sources
    const int* col = edge + E;   // targets

    __nv_bfloat16 *hA, *hB, *tbuf;
    cudaGetSymbolAddress((void**)&hA, g_hA);
    cudaGetSymbolAddress((void**)&hB, g_hB);
    cudaGetSymbolAddress((void**)&tbuf, g_t);
    unsigned char *whi, *wlo;
    cudaGetSymbolAddress((void**)&whi, g_whi);
    cudaGetSymbolAddress((void**)&wlo, g_wlo);

    cudaFuncSetAttribute(k_gemm_mma, cudaFuncAttributeMaxDynamicSharedMemorySize, SM_TOTAL);

    const int TB = 256;
    int nbScan = (n + SCANB - 1) / SCANB;
    int tiles = (n + 127) / 128;
    int cvtN = n * 32;           // float4 chunks of x

    // first GEMM kept at launch index 3 (the launch ncu -s 5 -c 1 captures)
    k_wprep<<<dim3(8, 4), 256>>>((const float*)d_in[3], (const float*)d_in[5],
                                 (const float*)d_in[7], (const float*)d_in[9]);  // 0
    k_init_cvt<<<(cvtN + TB - 1) / TB, TB>>>(x, hA, n);             // 1 (also converts x)
    k_hist<<<(E + TB - 1) / TB, TB>>>(col, E);                      // 2
    k_gemm_mma<<<tiles, 256, SM_TOTAL>>>(hA, whi, wlo, tbuf, n);    // 3  <- profiled
    k_scan1<<<nbScan, SCANB>>>(n);                                  // 4
    k_scan2<<<1, 128>>>(nbScan, n);                                 // 5
    k_scan3<<<nbScan, SCANB>>>(n);                                  // 6
    k_scatter<<<(E + TB - 1) / TB, TB>>>(row, col, E);              // 7
    k_gmin<<<(n + TB - 1) / TB, TB>>>(batch, n);                    // 8
    k_gfix<<<1, NG>>>();                                            // 9

    __nv_bfloat16* bufs[2] = {hB, hA};   // layer l output buffer = bufs[l & 1]
    // layer 1 tail
    k_spmm<<<(n + 7) / 8, 256>>>(tbuf, B[0], bufs[0], n);
    k_pool<<<NG, H>>>(bufs[0], 0);
    const __nv_bfloat16* hin = bufs[0];
    for (int l = 1; l < 5; ++l) {
        __nv_bfloat16* hout = bufs[l & 1];
        int widx = (l < 4) ? l : 3;      // layer 5 reuses W4
        k_gemm_mma<<<tiles, 256, SM_TOTAL>>>(hin, whi + (size_t)widx * 32768,
                                             wlo + (size_t)widx * 32768, tbuf, n);
        k_spmm<<<(n + 7) / 8, 256>>>(tbuf, B[l], hout, n);
        k_pool<<<NG, H>>>(hout, l * H);
        hin = hout;
    }
    k_mlp1<<<dim3(5, NG), H>>>(Wl1, bl1);
    k_mlp2<<<NG, H>>>(Wl2, bl2, out);
}

// round 10
// speedup vs baseline: 1.2901x; 1.2901x over previous
#include <cuda_runtime.h>
#include <cuda_bf16.h>
#include <cstdint>

#define H 128
#define NMAX 100000
#define EMAX 1600000
#define NG 512
#define SCANB 1024

// ---- scratch (static __device__ globals; no allocation allowed) ----
__device__ __align__(256) __nv_bfloat16 g_hA[(size_t)NMAX * H];
__device__ __align__(256) __nv_bfloat16 g_hB[(size_t)NMAX * H];
__device__ __align__(256) __nv_bfloat16 g_t[(size_t)NMAX * H];
__device__ float g_dinv[NMAX];
__device__ int   g_count[NMAX];
__device__ int   g_fill[NMAX];
__device__ int   g_rowptr[NMAX + 1];
__device__ int   g_src[EMAX];
__device__ int   g_gptr[NG + 1];
__device__ int   g_bsum[128];
__device__ int   g_boff[128];
__device__ float g_p[NG * 5 * H];
__device__ float g_q[NG * 5 * H];

__device__ __forceinline__ uint32_t smem_u32(const void* p) {
    uint32_t a;
    asm("{ .reg .u64 t; cvta.to.shared.u64 t, %1; cvt.u32.u64 %0, t; }" : "=r"(a) : "l"(p));
    return a;
}

#define LDSM_X4(r, addr) \
    asm volatile("ldmatrix.sync.aligned.m8n8.x4.shared.b16 {%0,%1,%2,%3}, [%4];" \
        : "=r"((r)[0]), "=r"((r)[1]), "=r"((r)[2]), "=r"((r)[3]) : "r"(addr))
#define LDSM_X4_T(r, addr) \
    asm volatile("ldmatrix.sync.aligned.m8n8.x4.trans.shared.b16 {%0,%1,%2,%3}, [%4];" \
        : "=r"((r)[0]), "=r"((r)[1]), "=r"((r)[2]), "=r"((r)[3]) : "r"(addr))
#define MMA_BF16(c, a, b0, b1) \
    asm volatile("mma.sync.aligned.m16n8k16.row.col.f32.bf16.bf16.f32 " \
        "{%0,%1,%2,%3}, {%4,%5,%6,%7}, {%8,%9}, {%0,%1,%2,%3};" \
        : "+f"((c)[0]), "+f"((c)[1]), "+f"((c)[2]), "+f"((c)[3]) \
        : "r"((a)[0]), "r"((a)[1]), "r"((a)[2]), "r"((a)[3]), "r"(b0), "r"(b1))

// 256B-row XOR swizzle: chunk[4:6] ^= row[0:2]  (rows at 256B stride)
#define SWZ(off) ((uint32_t)(off) ^ (((uint32_t)(off) >> 4) & 0x70))

__device__ __forceinline__ uint32_t pack2(float a, float b) {
    uint32_t lo = __bfloat16_as_ushort(__float2bfloat16_rn(a));
    uint32_t hi = __bfloat16_as_ushort(__float2bfloat16_rn(b));
    return lo | (hi << 16);
}

__device__ __forceinline__ float2 b2f(uint32_t u) {
    __nv_bfloat162 h = *reinterpret_cast<__nv_bfloat162*>(&u);
    return __bfloat1622float2(h);
}

// ---- preprocessing (init + convert x -> bf16 fused) ----
__global__ void k_init_cvt(const float* __restrict__ x, __nv_bfloat16* __restrict__ o, int n) {
    int i = blockIdx.x * blockDim.x + threadIdx.x;
    if (i < n) { g_count[i] = 0; g_fill[i] = 0; }
    if (i <= NG) g_gptr[i] = n;
    int total4 = n * 32;                  // float4 chunks of x
    if (i < total4) {
        float4 v = ((const float4*)x)[i];
        uint2 p;
        p.x = pack2(v.x, v.y);
        p.y = pack2(v.z, v.w);
        ((uint2*)o)[i] = p;
    }
}

__global__ void k_hist(const int* __restrict__ col, int E) {
    int i = blockIdx.x * blockDim.x + threadIdx.x;
    if (i < E) atomicAdd(&g_count[col[i]], 1);
}

__global__ void k_dinv(int n) {
    int i = blockIdx.x * blockDim.x + threadIdx.x;
    if (i < n) g_dinv[i] = rsqrtf((float)(g_count[i] + 1));
}

__global__ __launch_bounds__(SCANB) void k_scan1(int n) {
    __shared__ int warpsum[32];
    int gid = blockIdx.x * SCANB + threadIdx.x;
    int lane = threadIdx.x & 31, wid = threadIdx.x >> 5;
    int v = (gid < n) ? g_count[gid] : 0;
    int x = v;
#pragma unroll
    for (int d = 1; d < 32; d <<= 1) {
        int t = __shfl_up_sync(0xffffffffu, x, d);
        if (lane >= d) x += t;
    }
    if (lane == 31) warpsum[wid] = x;
    __syncthreads();
    if (wid == 0) {
        int s = warpsum[lane];
#pragma unroll
        for (int d = 1; d < 32; d <<= 1) {
            int t = __shfl_up_sync(0xffffffffu, s, d);
            if (lane >= d) s += t;
        }
        warpsum[lane] = s;
    }
    __syncthreads();
    int excl = x - v + (wid > 0 ? warpsum[wid - 1] : 0);
    if (gid < n) g_rowptr[gid] = excl;
    if (threadIdx.x == SCANB - 1) g_bsum[blockIdx.x] = warpsum[31];
}

__global__ void k_scan2(int nb, int n) {
    __shared__ int warpsum[4];
    int tid = threadIdx.x;
    int lane = tid & 31, wid = tid >> 5;
    int v = (tid < nb) ? g_bsum[tid] : 0;
    int x = v;
#pragma unroll
    for (int d = 1; d < 32; d <<= 1) {
        int t = __shfl_up_sync(0xffffffffu, x, d);
        if (lane >= d) x += t;
    }
    if (lane == 31) warpsum[wid] = x;
    __syncthreads();
    int base = 0;
    for (int w = 0; w < wid; ++w) base += warpsum[w];
    g_boff[tid] = base + x - v;
    if (tid == 127) g_rowptr[n] = base + x;
}

__global__ __launch_bounds__(SCANB) void k_scan3(int n) {
    int gid = blockIdx.x * SCANB + threadIdx.x;
    if (gid < n) g_rowptr[gid] += g_boff[blockIdx.x];
}

__global__ void k_scatter(const int* __restrict__ row, const int* __restrict__ col, int E) {
    int i = blockIdx.x * blockDim.x + threadIdx.x;
    if (i < E) {
        int c = col[i];
        int pos = g_rowptr[c] + atomicAdd(&g_fill[c], 1);
        g_src[pos] = row[i];
    }
}

__global__ void k_gmin(const int* __restrict__ batch, int n) {
    int i = blockIdx.x * blockDim.x + threadIdx.x;
    if (i < n) atomicMin(&g_gptr[batch[i]], i);
}

// parallel suffix-min over g_gptr[0..NG-1] with sentinel g_gptr[NG]=n
__global__ __launch_bounds__(NG) void k_gfix() {
    __shared__ int sm[NG + 1];
    int tid = threadIdx.x;
    sm[tid] = g_gptr[tid];
    if (tid == 0) sm[NG] = g_gptr[NG];
    __syncthreads();
    for (int d = 1; d <= NG; d <<= 1) {
        int v = (tid + d <= NG) ? sm[tid + d] : 0x7fffffff;
        __syncthreads();
        if (v < sm[tid]) sm[tid] = v;
        __syncthreads();
    }
    g_gptr[tid] = sm[tid];
}

// ---- HMMA GEMM: t[m,:] = bf16(dinv[m] * (A[m,:] @ W)), A bf16, W split hi/lo ----
// CTA tile 64x128, 8 warps (2x4 grid, warp tile 32x32); XOR-swizzled smem:
//   A 16KB, W hi/lo 32KB each = 80KB -> 2 CTAs/SM
#define SA     0
#define SW_HI  16384
#define SW_LO  49152
#define SM_TOTAL 81920

__global__ __launch_bounds__(256, 2) void k_gemm_mma(const __nv_bfloat16* __restrict__ A,
                                                     const float* __restrict__ W,
                                                     __nv_bfloat16* __restrict__ C, int nrows) {
    extern __shared__ char smem[];
    uint32_t sb = smem_u32(smem);
    int tid = threadIdx.x, lane = tid & 31, wid = tid >> 5;
    int wm = wid >> 2, wn = wid & 3;      // 2x4 warp grid; warp tile 32x32
    int m0 = blockIdx.x * 64;

    // prologue W: 128x128 fp32 -> bf16 hi/lo, swizzled 256B rows
#pragma unroll
    for (int j = 0; j < 8; ++j) {
        int idx = j * 256 + tid;          // 2048 items: k*16 + chunk
        int k = idx >> 4, c = idx & 15;
        float4 v0 = *(const float4*)&W[(size_t)k * H + c * 8];
        float4 v1 = *(const float4*)&W[(size_t)k * H + c * 8 + 4];
        __nv_bfloat16 h0 = __float2bfloat16_rn(v0.x), h1 = __float2bfloat16_rn(v0.y);
        __nv_bfloat16 h2 = __float2bfloat16_rn(v0.z), h3 = __float2bfloat16_rn(v0.w);
        __nv_bfloat16 h4 = __float2bfloat16_rn(v1.x), h5 = __float2bfloat16_rn(v1.y);
        __nv_bfloat16 h6 = __float2bfloat16_rn(v1.z), h7 = __float2bfloat16_rn(v1.w);
        uint4 hp, lp;
        hp.x = (uint32_t)__bfloat16_as_ushort(h0) | ((uint32_t)__bfloat16_as_ushort(h1) << 16);
        hp.y = (uint32_t)__bfloat16_as_ushort(h2) | ((uint32_t)__bfloat16_as_ushort(h3) << 16);
        hp.z = (uint32_t)__bfloat16_as_ushort(h4) | ((uint32_t)__bfloat16_as_ushort(h5) << 16);
        hp.w = (uint32_t)__bfloat16_as_ushort(h6) | ((uint32_t)__bfloat16_as_ushort(h7) << 16);
        lp.x = pack2(v0.x - __bfloat162float(h0), v0.y - __bfloat162float(h1));
        lp.y = pack2(v0.z - __bfloat162float(h2), v0.w - __bfloat162float(h3));
        lp.z = pack2(v1.x - __bfloat162float(h4), v1.y - __bfloat162float(h5));
        lp.w = pack2(v1.z - __bfloat162float(h6), v1.w - __bfloat162float(h7));
        uint32_t off = SWZ(k * 256 + c * 16);
        *(uint4*)(smem + SW_HI + off) = hp;
        *(uint4*)(smem + SW_LO + off) = lp;
    }
    // prologue A: 64 rows x 256B bf16, straight copy with swizzle
#pragma unroll
    for (int j = 0; j < 4; ++j) {
        int idx = j * 256 + tid;          // 1024 items: r*16 + chunk
        int r = idx >> 4, c = idx & 15;
        int m = m0 + r;
        uint4 v = make_uint4(0u, 0u, 0u, 0u);
        if (m < nrows) v = *(const uint4*)&A[(size_t)m * H + c * 8];
        *(uint4*)(smem + SA + SWZ(r * 256 + c * 16)) = v;
    }
    __syncthreads();

    float c[2][4][4];
#pragma unroll
    for (int mi = 0; mi < 2; ++mi)
#pragma unroll
        for (int nj = 0; nj < 4; ++nj)
#pragma unroll
            for (int q = 0; q < 4; ++q) c[mi][nj][q] = 0.f;

    int arow_lo = lane & 15;
    int asel = lane >> 4;

#pragma unroll
    for (int kc = 0; kc < 8; ++kc) {
        uint32_t a[2][4], bhi[2][4], blo[2][4];
#pragma unroll
        for (int mi = 0; mi < 2; ++mi) {
            int row = wm * 32 + mi * 16 + arow_lo;
            LDSM_X4(a[mi], sb + SA + SWZ(row * 256 + (kc * 2 + asel) * 16));
        }
#pragma unroll
        for (int ni = 0; ni < 2; ++ni) {
            int krow = kc * 16 + arow_lo;
            uint32_t off = SWZ(krow * 256 + (wn * 4 + ni * 2 + asel) * 16);
            LDSM_X4_T(bhi[ni], sb + SW_HI + off);
            LDSM_X4_T(blo[ni], sb + SW_LO + off);
        }
        // product 1: A x Whi
#pragma unroll
        for (int mi = 0; mi < 2; ++mi)
#pragma unroll
            for (int ni = 0; ni < 2; ++ni) {
                MMA_BF16(c[mi][2 * ni],     a[mi], bhi[ni][0], bhi[ni][1]);
                MMA_BF16(c[mi][2 * ni + 1], a[mi], bhi[ni][2], bhi[ni][3]);
            }
        // product 2: A x Wlo
#pragma unroll
        for (int mi = 0; mi < 2; ++mi)
#pragma unroll
            for (int ni = 0; ni < 2; ++ni) {
                MMA_BF16(c[mi][2 * ni],     a[mi], blo[ni][0], blo[ni][1]);
                MMA_BF16(c[mi][2 * ni + 1], a[mi], blo[ni][2], blo[ni][3]);
            }
    }

    // epilogue: scale by dinv, convert to bf16, store
#pragma unroll
    for (int mi = 0; mi < 2; ++mi) {
        int r = m0 + wm * 32 + mi * 16 + (lane >> 2);
        int r8 = r + 8;
        float d0 = (r < nrows) ? g_dinv[r] : 0.f;
        float d8 = (r8 < nrows) ? g_dinv[r8] : 0.f;
#pragma unroll
        for (int nj = 0; nj < 4; ++nj) {
            int col = wn * 32 + nj * 8 + (lane & 3) * 2;
            if (r < nrows)
                *(uint32_t*)&C[(size_t)r * H + col] = pack2(d0 * c[mi][nj][0], d0 * c[mi][nj][1]);
            if (r8 < nrows)
                *(uint32_t*)&C[(size_t)r8 * H + col] = pack2(d8 * c[mi][nj][2], d8 * c[mi][nj][3]);
        }
    }
}

// ---- SpMM: h[i] = bf16(relu(dinv[i]*(t[i] + sum_src t[src]) + b)), t bf16 ----
// 1 warp per node; lane covers 4 cols (uint2 = 4 bf16); 8 gathers in flight
__global__ __launch_bounds__(256) void k_spmm(const __nv_bfloat16* __restrict__ t,
                                              const float* __restrict__ bias,
                                              __nv_bfloat16* __restrict__ h, int n) {
    int node = (blockIdx.x * blockDim.x + threadIdx.x) >> 5;
    if (node >= n) return;
    int lane = threadIdx.x & 31;
    const uint2* __restrict__ t2 = (const uint2*)t;   // row = 32 uint2

    float di = g_dinv[node];
    int e0 = g_rowptr[node], e1 = g_rowptr[node + 1];
    uint2 sv = t2[(size_t)node * 32 + lane];
    float2 s0 = b2f(sv.x), s1 = b2f(sv.y);
    float ax = s0.x, ay = s0.y, az = s1.x, aw = s1.y;
    float bx = 0.f, by = 0.f, bz = 0.f, bw = 0.f;
    float cx = 0.f, cy = 0.f, cz = 0.f, cw = 0.f;
    float dx = 0.f, dy = 0.f, dz = 0.f, dw = 0.f;
    int e = e0;
    for (; e + 7 < e1; e += 8) {
        int i0 = g_src[e],     i1 = g_src[e + 1], i2 = g_src[e + 2], i3 = g_src[e + 3];
        int i4 = g_src[e + 4], i5 = g_src[e + 5], i6 = g_src[e + 6], i7 = g_src[e + 7];
        uint2 v0 = t2[(size_t)i0 * 32 + lane];
        uint2 v1 = t2[(size_t)i1 * 32 + lane];
        uint2 v2 = t2[(size_t)i2 * 32 + lane];
        uint2 v3 = t2[(size_t)i3 * 32 + lane];
        uint2 v4 = t2[(size_t)i4 * 32 + lane];
        uint2 v5 = t2[(size_t)i5 * 32 + lane];
        uint2 v6 = t2[(size_t)i6 * 32 + lane];
        uint2 v7 = t2[(size_t)i7 * 32 + lane];
        float2 p;
        p = b2f(v0.x); ax += p.x; ay += p.y;  p = b2f(v0.y); az += p.x; aw += p.y;
        p = b2f(v1.x); bx += p.x; by += p.y;  p = b2f(v1.y); bz += p.x; bw += p.y;
        p = b2f(v2.x); cx += p.x; cy += p.y;  p = b2f(v2.y); cz += p.x; cw += p.y;
        p = b2f(v3.x); dx += p.x; dy += p.y;  p = b2f(v3.y); dz += p.x; dw += p.y;
        p = b2f(v4.x); ax += p.x; ay += p.y;  p = b2f(v4.y); az += p.x; aw += p.y;
        p = b2f(v5.x); bx += p.x; by += p.y;  p = b2f(v5.y); bz += p.x; bw += p.y;
        p = b2f(v6.x); cx += p.x; cy += p.y;  p = b2f(v6.y); cz += p.x; cw += p.y;
        p = b2f(v7.x); dx += p.x; dy += p.y;  p = b2f(v7.y); dz += p.x; dw += p.y;
    }
    for (; e + 3 < e1; e += 4) {
        int i0 = g_src[e], i1 = g_src[e + 1], i2 = g_src[e + 2], i3 = g_src[e + 3];
        uint2 v0 = t2[(size_t)i0 * 32 + lane];
        uint2 v1 = t2[(size_t)i1 * 32 + lane];
        uint2 v2 = t2[(size_t)i2 * 32 + lane];
        uint2 v3 = t2[(size_t)i3 * 32 + lane];
        float2 p;
        p = b2f(v0.x); ax += p.x; ay += p.y;  p = b2f(v0.y); az += p.x; aw += p.y;
        p = b2f(v1.x); bx += p.x; by += p.y;  p = b2f(v1.y); bz += p.x; bw += p.y;
        p = b2f(v2.x); cx += p.x; cy += p.y;  p = b2f(v2.y); cz += p.x; cw += p.y;
        p = b2f(v3.x); dx += p.x; dy += p.y;  p = b2f(v3.y); dz += p.x; dw += p.y;
    }
    for (; e < e1; ++e) {
        int s = g_src[e];
        uint2 v = t2[(size_t)s * 32 + lane];
        float2 p;
        p = b2f(v.x); ax += p.x; ay += p.y;
        p = b2f(v.y); az += p.x; aw += p.y;
    }
    float4 bi = ((const float4*)bias)[lane];
    float r0 = fmaxf(fmaf(di, (ax + bx) + (cx + dx), bi.x), 0.f);
    float r1 = fmaxf(fmaf(di, (ay + by) + (cy + dy), bi.y), 0.f);
    float r2 = fmaxf(fmaf(di, (az + bz) + (cz + dz), bi.z), 0.f);
    float r3 = fmaxf(fmaf(di, (aw + bw) + (cw + dw), bi.w), 0.f);
    uint2 o;
    o.x = pack2(r0, r1);
    o.y = pack2(r2, r3);
    ((uint2*)h)[(size_t)node * 32 + lane] = o;
}

// ---- global mean pool (h bf16) ----
__global__ void k_pool(const __nv_bfloat16* __restrict__ h, int off) {
    int g = blockIdx.x, tx = threadIdx.x;
    int s = g_gptr[g], e = g_gptr[g + 1];
    float sum0 = 0.f, sum1 = 0.f;
    int i = s;
    for (; i + 1 < e; i += 2) {
        sum0 += __bfloat162float(h[(size_t)i * H + tx]);
        sum1 += __bfloat162float(h[(size_t)(i + 1) * H + tx]);
    }
    if (i < e) sum0 += __bfloat162float(h[(size_t)i * H + tx]);
    int cnt = e - s;
    g_p[g * (5 * H) + off + tx] = (sum0 + sum1) / (float)(cnt > 0 ? cnt : 1);
}

// ---- MLP head ----
__global__ void k_mlp1(const float* __restrict__ Wl1, const float* __restrict__ bl1) {
    __shared__ float ps[5 * H];
    int g = blockIdx.y;
    int j = blockIdx.x * H + threadIdx.x;
    for (int k = threadIdx.x; k < 5 * H; k += H) ps[k] = g_p[g * (5 * H) + k];
    __syncthreads();
    float acc = bl1[j];
    for (int k = 0; k < 5 * H; ++k) acc = fmaf(ps[k], Wl1[(size_t)k * (5 * H) + j], acc);
    g_q[g * (5 * H) + j] = fmaxf(acc, 0.f);
}

__global__ void k_mlp2(const float* __restrict__ Wl2, const float* __restrict__ bl2,
                       float* __restrict__ out) {
    __shared__ float red[H];
    int g = blockIdx.x, tid = threadIdx.x;
    float s = 0.f;
    for (int k = tid; k < 5 * H; k += H) s = fmaf(g_q[g * (5 * H) + k], Wl2[k], s);
    red[tid] = s;
    __syncthreads();
    for (int d = H / 2; d > 0; d >>= 1) {
        if (tid < d) red[tid] += red[tid + d];
        __syncthreads();
    }
    if (tid == 0) out[g] = red[0] + bl2[0];
}

// ---- launch ----
extern "C" void kernel_launch(void* const* d_in, const int* in_sizes, int n_in,
                              void* d_out, int out_size) {
    const float* x     = (const float*)d_in[0];
    const int*   edge  = (const int*)d_in[1];
    const int*   batch = (const int*)d_in[2];
    const float* W[5]  = {(const float*)d_in[3], (const float*)d_in[5],
                          (const float*)d_in[7], (const float*)d_in[9],
                          (const float*)d_in[9]};   // layer 5 reuses W4
    const float* B[5]  = {(const float*)d_in[4], (const float*)d_in[6],
                          (const float*)d_in[8], (const float*)d_in[10],
                          (const float*)d_in[10]};  // layer 5 reuses b4
    const float* Wl1 = (const float*)d_in[11];
    const float* bl1 = (const float*)d_in[12];
    const float* Wl2 = (const float*)d_in[13];
    const float* bl2 = (const float*)d_in[14];
    float* out = (float*)d_out;

    int n = in_sizes[0] / H;
    int E = in_sizes[1] / 2;
    const int* row = edge;       // sources
    const int* col = edge + E;   // targets

    __nv_bfloat16 *hA, *hB, *tbuf;
    cudaGetSymbolAddress((void**)&hA, g_hA);
    cudaGetSymbolAddress((void**)&hB, g_hB);
    cudaGetSymbolAddress((void**)&tbuf, g_t);

    cudaFuncSetAttribute(k_gemm_mma, cudaFuncAttributeMaxDynamicSharedMemorySize, SM_TOTAL);

    const int TB = 256;
    int nbScan = (n + SCANB - 1) / SCANB;
    int tiles = (n + 63) / 64;
    int cvtN = n * 32;           // float4 chunks of x

    // first GEMM kept at launch index 3 (the launch ncu -s 5 -c 1 captures)
    k_init_cvt<<<(cvtN + TB - 1) / TB, TB>>>(x, hA, n);             // 0 (also converts x)
    k_hist<<<(E + TB - 1) / TB, TB>>>(col, E);                      // 1
    k_dinv<<<(n + TB - 1) / TB, TB>>>(n);                           // 2
    k_gemm_mma<<<tiles, 256, SM_TOTAL>>>(hA, W[0], tbuf, n);        // 3  <- profiled
    k_scan1<<<nbScan, SCANB>>>(n);                                  // 4
    k_scan2<<<1, 128>>>(nbScan, n);                                 // 5
    k_scan3<<<nbScan, SCANB>>>(n);                                  // 6
    k_scatter<<<(E + TB - 1) / TB, TB>>>(row, col, E);              // 7
    k_gmin<<<(n + TB - 1) / TB, TB>>>(batch, n);                    // 8
    k_gfix<<<1, NG>>>();                                            // 9

    __nv_bfloat16* bufs[2] = {hB, hA};   // layer l output buffer = bufs[l & 1]
    // layer 1 tail
    k_spmm<<<(n + 7) / 8, 256>>>(tbuf, B[0], bufs[0], n);
    k_pool<<<NG, H>>>(bufs[0], 0);
    const __nv_bfloat16* hin = bufs[0];
    for (int l = 1; l < 5; ++l) {
        __nv_bfloat16* hout = bufs[l & 1];
        k_gemm_mma<<<tiles, 256, SM_TOTAL>>>(hin, W[l], tbuf, n);
        k_spmm<<<(n + 7) / 8, 256>>>(tbuf, B[l], hout, n);
        k_pool<<<NG, H>>>(hout, l * H);
        hin = hout;
    }
    k_mlp1<<<dim3(5, NG), H>>>(Wl1, bl1);
    k_mlp2<<<NG, H>>>(Wl2, bl2, out);
}

// round 11
// speedup vs baseline: 1.4058x; 1.0897x over previous
#include <cuda_runtime.h>
#include <cuda_bf16.h>
#include <cstdint>

#define H 128
#define NMAX 100000
#define EMAX 1600000
#define NG 512
#define SCANB 1024

// ---- scratch (static __device__ globals; no allocation allowed) ----
__device__ __align__(256) __nv_bfloat16 g_hA[(size_t)NMAX * H];
__device__ __align__(256) __nv_bfloat16 g_hB[(size_t)NMAX * H];
__device__ __align__(256) __nv_bfloat16 g_t[(size_t)NMAX * H];
__device__ float g_dinv[NMAX];
__device__ int   g_count[NMAX];
__device__ int   g_fill[NMAX];
__device__ int   g_rowptr[NMAX + 1];
__device__ int   g_src[EMAX];
__device__ int   g_gptr[NG + 1];
__device__ int   g_bsum[128];
__device__ int   g_boff[128];
__device__ float g_p[NG * 5 * H];
__device__ float g_q[NG * 5 * H];
// pre-split, pre-swizzled bf16 W images: 32KB per (layer, hi/lo)
__device__ __align__(16) unsigned char g_whi[4][32768];
__device__ __align__(16) unsigned char g_wlo[4][32768];

__device__ __forceinline__ uint32_t smem_u32(const void* p) {
    uint32_t a;
    asm("{ .reg .u64 t; cvta.to.shared.u64 t, %1; cvt.u32.u64 %0, t; }" : "=r"(a) : "l"(p));
    return a;
}

#define LDSM_X4(r, addr) \
    asm volatile("ldmatrix.sync.aligned.m8n8.x4.shared.b16 {%0,%1,%2,%3}, [%4];" \
        : "=r"((r)[0]), "=r"((r)[1]), "=r"((r)[2]), "=r"((r)[3]) : "r"(addr))
#define LDSM_X4_T(r, addr) \
    asm volatile("ldmatrix.sync.aligned.m8n8.x4.trans.shared.b16 {%0,%1,%2,%3}, [%4];" \
        : "=r"((r)[0]), "=r"((r)[1]), "=r"((r)[2]), "=r"((r)[3]) : "r"(addr))
#define MMA_BF16(c, a, b0, b1) \
    asm volatile("mma.sync.aligned.m16n8k16.row.col.f32.bf16.bf16.f32 " \
        "{%0,%1,%2,%3}, {%4,%5,%6,%7}, {%8,%9}, {%0,%1,%2,%3};" \
        : "+f"((c)[0]), "+f"((c)[1]), "+f"((c)[2]), "+f"((c)[3]) \
        : "r"((a)[0]), "r"((a)[1]), "r"((a)[2]), "r"((a)[3]), "r"(b0), "r"(b1))

// 256B-row XOR swizzle: chunk[4:6] ^= row[0:2]  (rows at 256B stride)
#define SWZ(off) ((uint32_t)(off) ^ (((uint32_t)(off) >> 4) & 0x70))

__device__ __forceinline__ uint32_t pack2(float a, float b) {
    uint32_t lo = __bfloat16_as_ushort(__float2bfloat16_rn(a));
    uint32_t hi = __bfloat16_as_ushort(__float2bfloat16_rn(b));
    return lo | (hi << 16);
}

__device__ __forceinline__ float2 b2f(uint32_t u) {
    __nv_bfloat162 h = *reinterpret_cast<__nv_bfloat162*>(&u);
    return __bfloat1622float2(h);
}

// split 8 fp32 (two float4) into 16B hi + 16B lo bf16 images
__device__ __forceinline__ void split8(float4 v0, float4 v1, uint4& hp, uint4& lp) {
    __nv_bfloat16 h0 = __float2bfloat16_rn(v0.x), h1 = __float2bfloat16_rn(v0.y);
    __nv_bfloat16 h2 = __float2bfloat16_rn(v0.z), h3 = __float2bfloat16_rn(v0.w);
    __nv_bfloat16 h4 = __float2bfloat16_rn(v1.x), h5 = __float2bfloat16_rn(v1.y);
    __nv_bfloat16 h6 = __float2bfloat16_rn(v1.z), h7 = __float2bfloat16_rn(v1.w);
    hp.x = (uint32_t)__bfloat16_as_ushort(h0) | ((uint32_t)__bfloat16_as_ushort(h1) << 16);
    hp.y = (uint32_t)__bfloat16_as_ushort(h2) | ((uint32_t)__bfloat16_as_ushort(h3) << 16);
    hp.z = (uint32_t)__bfloat16_as_ushort(h4) | ((uint32_t)__bfloat16_as_ushort(h5) << 16);
    hp.w = (uint32_t)__bfloat16_as_ushort(h6) | ((uint32_t)__bfloat16_as_ushort(h7) << 16);
    lp.x = pack2(v0.x - __bfloat162float(h0), v0.y - __bfloat162float(h1));
    lp.y = pack2(v0.z - __bfloat162float(h2), v0.w - __bfloat162float(h3));
    lp.z = pack2(v1.x - __bfloat162float(h4), v1.y - __bfloat162float(h5));
    lp.w = pack2(v1.z - __bfloat162float(h6), v1.w - __bfloat162float(h7));
}

// ---- W prep: fp32 [128][128] -> pre-swizzled bf16 hi/lo images (per layer) ----
__global__ void k_wprep(const float* __restrict__ W0, const float* __restrict__ W1,
                        const float* __restrict__ W2, const float* __restrict__ W3) {
    const float* Ws[4] = {W0, W1, W2, W3};
    int layer = blockIdx.y;
    int idx = blockIdx.x * blockDim.x + threadIdx.x;   // 0..2047 = k*16 + chunk
    int k = idx >> 4, c = idx & 15;
    const float* W = Ws[layer];
    float4 v0 = *(const float4*)&W[(size_t)k * H + c * 8];
    float4 v1 = *(const float4*)&W[(size_t)k * H + c * 8 + 4];
    uint4 hp, lp;
    split8(v0, v1, hp, lp);
    uint32_t off = SWZ(k * 256 + c * 16);
    *(uint4*)&g_whi[layer][off] = hp;
    *(uint4*)&g_wlo[layer][off] = lp;
}

// ---- preprocessing (init + convert x -> bf16 fused) ----
__global__ void k_init_cvt(const float* __restrict__ x, __nv_bfloat16* __restrict__ o, int n) {
    int i = blockIdx.x * blockDim.x + threadIdx.x;
    if (i < n) { g_count[i] = 0; g_fill[i] = 0; }
    if (i <= NG) g_gptr[i] = n;
    int total4 = n * 32;                  // float4 chunks of x
    if (i < total4) {
        float4 v = ((const float4*)x)[i];
        uint2 p;
        p.x = pack2(v.x, v.y);
        p.y = pack2(v.z, v.w);
        ((uint2*)o)[i] = p;
    }
}

__global__ void k_hist(const int* __restrict__ col, int E) {
    int i = blockIdx.x * blockDim.x + threadIdx.x;
    if (i < E) atomicAdd(&g_count[col[i]], 1);
}

__global__ void k_dinv(int n) {
    int i = blockIdx.x * blockDim.x + threadIdx.x;
    if (i < n) g_dinv[i] = rsqrtf((float)(g_count[i] + 1));
}

__global__ __launch_bounds__(SCANB) void k_scan1(int n) {
    __shared__ int warpsum[32];
    int gid = blockIdx.x * SCANB + threadIdx.x;
    int lane = threadIdx.x & 31, wid = threadIdx.x >> 5;
    int v = (gid < n) ? g_count[gid] : 0;
    int x = v;
#pragma unroll
    for (int d = 1; d < 32; d <<= 1) {
        int t = __shfl_up_sync(0xffffffffu, x, d);
        if (lane >= d) x += t;
    }
    if (lane == 31) warpsum[wid] = x;
    __syncthreads();
    if (wid == 0) {
        int s = warpsum[lane];
#pragma unroll
        for (int d = 1; d < 32; d <<= 1) {
            int t = __shfl_up_sync(0xffffffffu, s, d);
            if (lane >= d) s += t;
        }
        warpsum[lane] = s;
    }
    __syncthreads();
    int excl = x - v + (wid > 0 ? warpsum[wid - 1] : 0);
    if (gid < n) g_rowptr[gid] = excl;
    if (threadIdx.x == SCANB - 1) g_bsum[blockIdx.x] = warpsum[31];
}

__global__ void k_scan2(int nb, int n) {
    __shared__ int warpsum[4];
    int tid = threadIdx.x;
    int lane = tid & 31, wid = tid >> 5;
    int v = (tid < nb) ? g_bsum[tid] : 0;
    int x = v;
#pragma unroll
    for (int d = 1; d < 32; d <<= 1) {
        int t = __shfl_up_sync(0xffffffffu, x, d);
        if (lane >= d) x += t;
    }
    if (lane == 31) warpsum[wid] = x;
    __syncthreads();
    int base = 0;
    for (int w = 0; w < wid; ++w) base += warpsum[w];
    g_boff[tid] = base + x - v;
    if (tid == 127) g_rowptr[n] = base + x;
}

__global__ __launch_bounds__(SCANB) void k_scan3(int n) {
    int gid = blockIdx.x * SCANB + threadIdx.x;
    if (gid < n) g_rowptr[gid] += g_boff[blockIdx.x];
}

__global__ void k_scatter(const int* __restrict__ row, const int* __restrict__ col, int E) {
    int i = blockIdx.x * blockDim.x + threadIdx.x;
    if (i < E) {
        int c = col[i];
        int pos = g_rowptr[c] + atomicAdd(&g_fill[c], 1);
        g_src[pos] = row[i];
    }
}

__global__ void k_gmin(const int* __restrict__ batch, int n) {
    int i = blockIdx.x * blockDim.x + threadIdx.x;
    if (i < n) atomicMin(&g_gptr[batch[i]], i);
}

// parallel suffix-min over g_gptr[0..NG-1] with sentinel g_gptr[NG]=n
__global__ __launch_bounds__(NG) void k_gfix() {
    __shared__ int sm[NG + 1];
    int tid = threadIdx.x;
    sm[tid] = g_gptr[tid];
    if (tid == 0) sm[NG] = g_gptr[NG];
    __syncthreads();
    for (int d = 1; d <= NG; d <<= 1) {
        int v = (tid + d <= NG) ? sm[tid + d] : 0x7fffffff;
        __syncthreads();
        if (v < sm[tid]) sm[tid] = v;
        __syncthreads();
    }
    g_gptr[tid] = sm[tid];
}

// ---- HMMA GEMM: t[m,:] = bf16(dinv[m] * (A[m,:] @ W)), A bf16, W pre-split ----
// CTA tile 64x128, 8 warps (2x4 grid, warp tile 32x32); XOR-swizzled smem:
//   A 16KB, W hi/lo 32KB each = 80KB -> 2 CTAs/SM   (mainloop identical to R8)
#define SA     0
#define SW_HI  16384
#define SW_LO  49152
#define SM_TOTAL 81920

__global__ __launch_bounds__(256, 2) void k_gemm_mma(const __nv_bfloat16* __restrict__ A,
                                                     const unsigned char* __restrict__ Whi,
                                                     const unsigned char* __restrict__ Wlo,
                                                     __nv_bfloat16* __restrict__ C, int nrows) {
    extern __shared__ char smem[];
    uint32_t sb = smem_u32(smem);
    int tid = threadIdx.x, lane = tid & 31, wid = tid >> 5;
    int wm = wid >> 2, wn = wid & 3;      // 2x4 warp grid; warp tile 32x32
    int m0 = blockIdx.x * 64;

    // prologue W: straight byte copy of pre-split, pre-swizzled images
    {
        const uint4* __restrict__ s1 = (const uint4*)Whi;
        const uint4* __restrict__ s2 = (const uint4*)Wlo;
        uint4* d1 = (uint4*)(smem + SW_HI);
        uint4* d2 = (uint4*)(smem + SW_LO);
#pragma unroll
        for (int j = 0; j < 8; ++j) {
            int i = j * 256 + tid;
            d1[i] = s1[i];
            d2[i] = s2[i];
        }
    }
    // prologue A: 64 rows x 256B bf16, straight copy with swizzle
#pragma unroll
    for (int j = 0; j < 4; ++j) {
        int idx = j * 256 + tid;          // 1024 items: r*16 + chunk
        int r = idx >> 4, c = idx & 15;
        int m = m0 + r;
        uint4 v = make_uint4(0u, 0u, 0u, 0u);
        if (m < nrows) v = *(const uint4*)&A[(size_t)m * H + c * 8];
        *(uint4*)(smem + SA + SWZ(r * 256 + c * 16)) = v;
    }
    __syncthreads();

    float c[2][4][4];
#pragma unroll
    for (int mi = 0; mi < 2; ++mi)
#pragma unroll
        for (int nj = 0; nj < 4; ++nj)
#pragma unroll
            for (int q = 0; q < 4; ++q) c[mi][nj][q] = 0.f;

    int arow_lo = lane & 15;
    int asel = lane >> 4;

#pragma unroll
    for (int kc = 0; kc < 8; ++kc) {
        uint32_t a[2][4], bhi[2][4], blo[2][4];
#pragma unroll
        for (int mi = 0; mi < 2; ++mi) {
            int row = wm * 32 + mi * 16 + arow_lo;
            LDSM_X4(a[mi], sb + SA + SWZ(row * 256 + (kc * 2 + asel) * 16));
        }
#pragma unroll
        for (int ni = 0; ni < 2; ++ni) {
            int krow = kc * 16 + arow_lo;
            uint32_t off = SWZ(krow * 256 + (wn * 4 + ni * 2 + asel) * 16);
            LDSM_X4_T(bhi[ni], sb + SW_HI + off);
            LDSM_X4_T(blo[ni], sb + SW_LO + off);
        }
        // product 1: A x Whi
#pragma unroll
        for (int mi = 0; mi < 2; ++mi)
#pragma unroll
            for (int ni = 0; ni < 2; ++ni) {
                MMA_BF16(c[mi][2 * ni],     a[mi], bhi[ni][0], bhi[ni][1]);
                MMA_BF16(c[mi][2 * ni + 1], a[mi], bhi[ni][2], bhi[ni][3]);
            }
        // product 2: A x Wlo
#pragma unroll
        for (int mi = 0; mi < 2; ++mi)
#pragma unroll
            for (int ni = 0; ni < 2; ++ni) {
                MMA_BF16(c[mi][2 * ni],     a[mi], blo[ni][0], blo[ni][1]);
                MMA_BF16(c[mi][2 * ni + 1], a[mi], blo[ni][2], blo[ni][3]);
            }
    }

    // epilogue: scale by dinv (inline rsqrt of degree, same op as k_dinv), store bf16
#pragma unroll
    for (int mi = 0; mi < 2; ++mi) {
        int r = m0 + wm * 32 + mi * 16 + (lane >> 2);
        int r8 = r + 8;
        float d0 = (r < nrows) ? rsqrtf((float)(g_count[r] + 1)) : 0.f;
        float d8 = (r8 < nrows) ? rsqrtf((float)(g_count[r8] + 1)) : 0.f;
#pragma unroll
        for (int nj = 0; nj < 4; ++nj) {
            int col = wn * 32 + nj * 8 + (lane & 3) * 2;
            if (r < nrows)
                *(uint32_t*)&C[(size_t)r * H + col] = pack2(d0 * c[mi][nj][0], d0 * c[mi][nj][1]);
            if (r8 < nrows)
                *(uint32_t*)&C[(size_t)r8 * H + col] = pack2(d8 * c[mi][nj][2], d8 * c[mi][nj][3]);
        }
    }
}

// ---- SpMM: h[i] = bf16(relu(dinv[i]*(t[i] + sum_src t[src]) + b)), t bf16 ----
// 1 warp per node; lane covers 4 cols (uint2 = 4 bf16)   [exact R8 version]
__global__ __launch_bounds__(256) void k_spmm(const __nv_bfloat16* __restrict__ t,
                                              const float* __restrict__ bias,
                                              __nv_bfloat16* __restrict__ h, int n) {
    int node = (blockIdx.x * blockDim.x + threadIdx.x) >> 5;
    if (node >= n) return;
    int lane = threadIdx.x & 31;
    const uint2* __restrict__ t2 = (const uint2*)t;   // row = 32 uint2

    float di = g_dinv[node];
    int e0 = g_rowptr[node], e1 = g_rowptr[node + 1];
    uint2 sv = t2[(size_t)node * 32 + lane];
    float2 s0 = b2f(sv.x), s1 = b2f(sv.y);
    float ax = s0.x, ay = s0.y, az = s1.x, aw = s1.y;
    float bx = 0.f, by = 0.f, bz = 0.f, bw = 0.f;
    float cx = 0.f, cy = 0.f, cz = 0.f, cw = 0.f;
    float dx = 0.f, dy = 0.f, dz = 0.f, dw = 0.f;
    int e = e0;
    for (; e + 3 < e1; e += 4) {
        int i0 = g_src[e], i1 = g_src[e + 1], i2 = g_src[e + 2], i3 = g_src[e + 3];
        uint2 v0 = t2[(size_t)i0 * 32 + lane];
        uint2 v1 = t2[(size_t)i1 * 32 + lane];
        uint2 v2 = t2[(size_t)i2 * 32 + lane];
        uint2 v3 = t2[(size_t)i3 * 32 + lane];
        float2 p;
        p = b2f(v0.x); ax += p.x; ay += p.y;  p = b2f(v0.y); az += p.x; aw += p.y;
        p = b2f(v1.x); bx += p.x; by += p.y;  p = b2f(v1.y); bz += p.x; bw += p.y;
        p = b2f(v2.x); cx += p.x; cy += p.y;  p = b2f(v2.y); cz += p.x; cw += p.y;
        p = b2f(v3.x); dx += p.x; dy += p.y;  p = b2f(v3.y); dz += p.x; dw += p.y;
    }
    for (; e < e1; ++e) {
        int s = g_src[e];
        uint2 v = t2[(size_t)s * 32 + lane];
        float2 p;
        p = b2f(v.x); ax += p.x; ay += p.y;
        p = b2f(v.y); az += p.x; aw += p.y;
    }
    float4 bi = ((const float4*)bias)[lane];
    float r0 = fmaxf(fmaf(di, (ax + bx) + (cx + dx), bi.x), 0.f);
    float r1 = fmaxf(fmaf(di, (ay + by) + (cy + dy), bi.y), 0.f);
    float r2 = fmaxf(fmaf(di, (az + bz) + (cz + dz), bi.z), 0.f);
    float r3 = fmaxf(fmaf(di, (aw + bw) + (cw + dw), bi.w), 0.f);
    uint2 o;
    o.x = pack2(r0, r1);
    o.y = pack2(r2, r3);
    ((uint2*)h)[(size_t)node * 32 + lane] = o;
}

// ---- global mean pool (h bf16)   [exact R8 version] ----
__global__ void k_pool(const __nv_bfloat16* __restrict__ h, int off) {
    int g = blockIdx.x, tx = threadIdx.x;
    int s = g_gptr[g], e = g_gptr[g + 1];
    float sum = 0.f;
    for (int i = s; i < e; ++i) sum += __bfloat162float(h[(size_t)i * H + tx]);
    int cnt = e - s;
    g_p[g * (5 * H) + off + tx] = sum / (float)(cnt > 0 ? cnt : 1);
}

// ---- MLP head ----
__global__ void k_mlp1(const float* __restrict__ Wl1, const float* __restrict__ bl1) {
    __shared__ float ps[5 * H];
    int g = blockIdx.y;
    int j = blockIdx.x * H + threadIdx.x;
    for (int k = threadIdx.x; k < 5 * H; k += H) ps[k] = g_p[g * (5 * H) + k];
    __syncthreads();
    float acc = bl1[j];
    for (int k = 0; k < 5 * H; ++k) acc = fmaf(ps[k], Wl1[(size_t)k * (5 * H) + j], acc);
    g_q[g * (5 * H) + j] = fmaxf(acc, 0.f);
}

__global__ void k_mlp2(const float* __restrict__ Wl2, const float* __restrict__ bl2,
                       float* __restrict__ out) {
    __shared__ float red[H];
    int g = blockIdx.x, tid = threadIdx.x;
    float s = 0.f;
    for (int k = tid; k < 5 * H; k += H) s = fmaf(g_q[g * (5 * H) + k], Wl2[k], s);
    red[tid] = s;
    __syncthreads();
    for (int d = H / 2; d > 0; d >>= 1) {
        if (tid < d) red[tid] += red[tid + d];
        __syncthreads();
    }
    if (tid == 0) out[g] = red[0] + bl2[0];
}

// ---- launch ----
extern "C" void kernel_launch(void* const* d_in, const int* in_sizes, int n_in,
                              void* d_out, int out_size) {
    const float* x     = (const float*)d_in[0];
    const int*   edge  = (const int*)d_in[1];
    const int*   batch = (const int*)d_in[2];
    const float* B[5]  = {(const float*)d_in[4], (const float*)d_in[6],
                          (const float*)d_in[8], (const float*)d_in[10],
                          (const float*)d_in[10]};  // layer 5 reuses b4
    const float* Wl1 = (const float*)d_in[11];
    const float* bl1 = (const float*)d_in[12];
    const float* Wl2 = (const float*)d_in[13];
    const float* bl2 = (const float*)d_in[14];
    float* out = (float*)d_out;

    int n = in_sizes[0] / H;
    int E = in_sizes[1] / 2;
    const int* row = edge;       // sources
    const int* col = edge + E;   // targets

    __nv_bfloat16 *hA, *hB, *tbuf;
    cudaGetSymbolAddress((void**)&hA, g_hA);
    cudaGetSymbolAddress((void**)&hB, g_hB);
    cudaGetSymbolAddress((void**)&tbuf, g_t);
    unsigned char *whi, *wlo;
    cudaGetSymbolAddress((void**)&whi, g_whi);
    cudaGetSymbolAddress((void**)&wlo, g_wlo);

    cudaFuncSetAttribute(k_gemm_mma, cudaFuncAttributeMaxDynamicSharedMemorySize, SM_TOTAL);

    const int TB = 256;
    int nbScan = (n + SCANB - 1) / SCANB;
    int tiles = (n + 63) / 64;
    int cvtN = n * 32;           // float4 chunks of x

    // first GEMM kept at launch index 3 (the launch ncu -s 5 -c 1 captures);
    // GEMM no longer needs g_dinv (inline rsqrt), so k_dinv moves after it.
    k_wprep<<<dim3(8, 4), 256>>>((const float*)d_in[3], (const float*)d_in[5],
                                 (const float*)d_in[7], (const float*)d_in[9]);  // 0
    k_init_cvt<<<(cvtN + TB - 1) / TB, TB>>>(x, hA, n);             // 1 (also converts x)
    k_hist<<<(E + TB - 1) / TB, TB>>>(col, E);                      // 2
    k_gemm_mma<<<tiles, 256, SM_TOTAL>>>(hA, whi, wlo, tbuf, n);    // 3  <- profiled
    k_dinv<<<(n + TB - 1) / TB, TB>>>(n);                           // 4 (for spmm)
    k_scan1<<<nbScan, SCANB>>>(n);                                  // 5
    k_scan2<<<1, 128>>>(nbScan, n);                                 // 6
    k_scan3<<<nbScan, SCANB>>>(n);                                  // 7
    k_scatter<<<(E + TB - 1) / TB, TB>>>(row, col, E);              // 8
    k_gmin<<<(n + TB - 1) / TB, TB>>>(batch, n);                    // 9
    k_gfix<<<1, NG>>>();                                            // 10

    __nv_bfloat16* bufs[2] = {hB, hA};   // layer l output buffer = bufs[l & 1]
    // layer 1 tail
    k_spmm<<<(n + 7) / 8, 256>>>(tbuf, B[0], bufs[0], n);
    k_pool<<<NG, H>>>(bufs[0], 0);
    const __nv_bfloat16* hin = bufs[0];
    for (int l = 1; l < 5; ++l) {
        __nv_bfloat16* hout = bufs[l & 1];
        int widx = (l < 4) ? l : 3;      // layer 5 reuses W4
        k_gemm_mma<<<tiles, 256, SM_TOTAL>>>(hin, whi + (size_t)widx * 32768,
                                             wlo + (size_t)widx * 32768, tbuf, n);
        k_spmm<<<(n + 7) / 8, 256>>>(tbuf, B[l], hout, n);
        k_pool<<<NG, H>>>(hout, l * H);
        hin = hout;
    }
    k_mlp1<<<dim3(5, NG), H>>>(Wl1, bl1);
    k_mlp2<<<NG, H>>>(Wl2, bl2, out);
}

// round 12
// speedup vs baseline: 1.4617x; 1.0398x over previous
#include <cuda_runtime.h>
#include <cuda_bf16.h>
#include <cstdint>

#define H 128
#define NMAX 100000
#define EMAX 1600000
#define NG 512
#define SCANB 1024

// ---- scratch (static __device__ globals; no allocation allowed) ----
__device__ __align__(256) __nv_bfloat16 g_hA[(size_t)NMAX * H];
__device__ __align__(256) __nv_bfloat16 g_hB[(size_t)NMAX * H];
__device__ __align__(256) __nv_bfloat16 g_t[(size_t)NMAX * H];
__device__ float g_dinv[NMAX];
__device__ int   g_count[NMAX];
__device__ int   g_fill[NMAX];
__device__ int   g_rowptr[NMAX + 1];
__device__ int   g_src[EMAX];
__device__ int   g_gptr[NG + 1];
__device__ int   g_bsum[128];
__device__ int   g_boff[128];
__device__ float g_p[NG * 5 * H];
__device__ float g_q[NG * 5 * H];
// pre-split, pre-swizzled bf16 W images: 32KB per (layer, hi/lo)
__device__ __align__(16) unsigned char g_whi[4][32768];
__device__ __align__(16) unsigned char g_wlo[4][32768];

__device__ __forceinline__ uint32_t smem_u32(const void* p) {
    uint32_t a;
    asm("{ .reg .u64 t; cvta.to.shared.u64 t, %1; cvt.u32.u64 %0, t; }" : "=r"(a) : "l"(p));
    return a;
}

#define LDSM_X4(r, addr) \
    asm volatile("ldmatrix.sync.aligned.m8n8.x4.shared.b16 {%0,%1,%2,%3}, [%4];" \
        : "=r"((r)[0]), "=r"((r)[1]), "=r"((r)[2]), "=r"((r)[3]) : "r"(addr))
#define LDSM_X4_T(r, addr) \
    asm volatile("ldmatrix.sync.aligned.m8n8.x4.trans.shared.b16 {%0,%1,%2,%3}, [%4];" \
        : "=r"((r)[0]), "=r"((r)[1]), "=r"((r)[2]), "=r"((r)[3]) : "r"(addr))
#define MMA_BF16(c, a, b0, b1) \
    asm volatile("mma.sync.aligned.m16n8k16.row.col.f32.bf16.bf16.f32 " \
        "{%0,%1,%2,%3}, {%4,%5,%6,%7}, {%8,%9}, {%0,%1,%2,%3};" \
        : "+f"((c)[0]), "+f"((c)[1]), "+f"((c)[2]), "+f"((c)[3]) \
        : "r"((a)[0]), "r"((a)[1]), "r"((a)[2]), "r"((a)[3]), "r"(b0), "r"(b1))

// 256B-row XOR swizzle: chunk[4:6] ^= row[0:2]  (rows at 256B stride)
#define SWZ(off) ((uint32_t)(off) ^ (((uint32_t)(off) >> 4) & 0x70))

__device__ __forceinline__ uint32_t pack2(float a, float b) {
    uint32_t lo = __bfloat16_as_ushort(__float2bfloat16_rn(a));
    uint32_t hi = __bfloat16_as_ushort(__float2bfloat16_rn(b));
    return lo | (hi << 16);
}

__device__ __forceinline__ float2 b2f(uint32_t u) {
    __nv_bfloat162 h = *reinterpret_cast<__nv_bfloat162*>(&u);
    return __bfloat1622float2(h);
}

// split 8 fp32 (two float4) into 16B hi + 16B lo bf16 images
__device__ __forceinline__ void split8(float4 v0, float4 v1, uint4& hp, uint4& lp) {
    __nv_bfloat16 h0 = __float2bfloat16_rn(v0.x), h1 = __float2bfloat16_rn(v0.y);
    __nv_bfloat16 h2 = __float2bfloat16_rn(v0.z), h3 = __float2bfloat16_rn(v0.w);
    __nv_bfloat16 h4 = __float2bfloat16_rn(v1.x), h5 = __float2bfloat16_rn(v1.y);
    __nv_bfloat16 h6 = __float2bfloat16_rn(v1.z), h7 = __float2bfloat16_rn(v1.w);
    hp.x = (uint32_t)__bfloat16_as_ushort(h0) | ((uint32_t)__bfloat16_as_ushort(h1) << 16);
    hp.y = (uint32_t)__bfloat16_as_ushort(h2) | ((uint32_t)__bfloat16_as_ushort(h3) << 16);
    hp.z = (uint32_t)__bfloat16_as_ushort(h4) | ((uint32_t)__bfloat16_as_ushort(h5) << 16);
    hp.w = (uint32_t)__bfloat16_as_ushort(h6) | ((uint32_t)__bfloat16_as_ushort(h7) << 16);
    lp.x = pack2(v0.x - __bfloat162float(h0), v0.y - __bfloat162float(h1));
    lp.y = pack2(v0.z - __bfloat162float(h2), v0.w - __bfloat162float(h3));
    lp.z = pack2(v1.x - __bfloat162float(h4), v1.y - __bfloat162float(h5));
    lp.w = pack2(v1.z - __bfloat162float(h6), v1.w - __bfloat162float(h7));
}

// ---- W prep: fp32 [128][128] -> pre-swizzled bf16 hi/lo images (per layer) ----
__global__ void k_wprep(const float* __restrict__ W0, const float* __restrict__ W1,
                        const float* __restrict__ W2, const float* __restrict__ W3) {
    const float* Ws[4] = {W0, W1, W2, W3};
    int layer = blockIdx.y;
    int idx = blockIdx.x * blockDim.x + threadIdx.x;   // 0..2047 = k*16 + chunk
    int k = idx >> 4, c = idx & 15;
    const float* W = Ws[layer];
    float4 v0 = *(const float4*)&W[(size_t)k * H + c * 8];
    float4 v1 = *(const float4*)&W[(size_t)k * H + c * 8 + 4];
    uint4 hp, lp;
    split8(v0, v1, hp, lp);
    uint32_t off = SWZ(k * 256 + c * 16);
    *(uint4*)&g_whi[layer][off] = hp;
    *(uint4*)&g_wlo[layer][off] = lp;
}

// ---- preprocessing (init + convert x -> bf16 + zero g_p, fused) ----
__global__ void k_init_cvt(const float* __restrict__ x, __nv_bfloat16* __restrict__ o, int n) {
    int i = blockIdx.x * blockDim.x + threadIdx.x;
    if (i < n) { g_count[i] = 0; g_fill[i] = 0; }
    if (i <= NG) g_gptr[i] = n;
    if (i < NG * 5 * H) g_p[i] = 0.f;
    int total4 = n * 32;                  // float4 chunks of x
    if (i < total4) {
        float4 v = ((const float4*)x)[i];
        uint2 p;
        p.x = pack2(v.x, v.y);
        p.y = pack2(v.z, v.w);
        ((uint2*)o)[i] = p;
    }
}

// hist over edges + gmin over nodes, fused (E >= n)
__global__ void k_hist_gmin(const int* __restrict__ col, const int* __restrict__ batch,
                            int E, int n) {
    int i = blockIdx.x * blockDim.x + threadIdx.x;
    if (i < E) atomicAdd(&g_count[col[i]], 1);
    if (i < n) atomicMin(&g_gptr[batch[i]], i);
}

__global__ __launch_bounds__(SCANB) void k_scan1(int n) {
    __shared__ int warpsum[32];
    int gid = blockIdx.x * SCANB + threadIdx.x;
    int lane = threadIdx.x & 31, wid = threadIdx.x >> 5;
    int v = (gid < n) ? g_count[gid] : 0;
    if (gid < n) g_dinv[gid] = rsqrtf((float)(v + 1));   // fused dinv
    int x = v;
#pragma unroll
    for (int d = 1; d < 32; d <<= 1) {
        int t = __shfl_up_sync(0xffffffffu, x, d);
        if (lane >= d) x += t;
    }
    if (lane == 31) warpsum[wid] = x;
    __syncthreads();
    if (wid == 0) {
        int s = warpsum[lane];
#pragma unroll
        for (int d = 1; d < 32; d <<= 1) {
            int t = __shfl_up_sync(0xffffffffu, s, d);
            if (lane >= d) s += t;
        }
        warpsum[lane] = s;
    }
    __syncthreads();
    int excl = x - v + (wid > 0 ? warpsum[wid - 1] : 0);
    if (gid < n) g_rowptr[gid] = excl;
    if (threadIdx.x == SCANB - 1) g_bsum[blockIdx.x] = warpsum[31];
}

__global__ void k_scan2(int nb, int n) {
    __shared__ int warpsum[4];
    int tid = threadIdx.x;
    int lane = tid & 31, wid = tid >> 5;
    int v = (tid < nb) ? g_bsum[tid] : 0;
    int x = v;
#pragma unroll
    for (int d = 1; d < 32; d <<= 1) {
        int t = __shfl_up_sync(0xffffffffu, x, d);
        if (lane >= d) x += t;
    }
    if (lane == 31) warpsum[wid] = x;
    __syncthreads();
    int base = 0;
    for (int w = 0; w < wid; ++w) base += warpsum[w];
    g_boff[tid] = base + x - v;
    if (tid == 127) g_rowptr[n] = base + x;
}

__global__ __launch_bounds__(SCANB) void k_scan3(int n) {
    int gid = blockIdx.x * SCANB + threadIdx.x;
    if (gid < n) g_rowptr[gid] += g_boff[blockIdx.x];
}

__global__ void k_scatter(const int* __restrict__ row, const int* __restrict__ col, int E) {
    int i = blockIdx.x * blockDim.x + threadIdx.x;
    if (i < E) {
        int c = col[i];
        int pos = g_rowptr[c] + atomicAdd(&g_fill[c], 1);
        g_src[pos] = row[i];
    }
}

// parallel suffix-min over g_gptr[0..NG-1] with sentinel g_gptr[NG]=n
__global__ __launch_bounds__(NG) void k_gfix() {
    __shared__ int sm[NG + 1];
    int tid = threadIdx.x;
    sm[tid] = g_gptr[tid];
    if (tid == 0) sm[NG] = g_gptr[NG];
    __syncthreads();
    for (int d = 1; d <= NG; d <<= 1) {
        int v = (tid + d <= NG) ? sm[tid + d] : 0x7fffffff;
        __syncthreads();
        if (v < sm[tid]) sm[tid] = v;
        __syncthreads();
    }
    g_gptr[tid] = sm[tid];
}

// ---- HMMA GEMM: t[m,:] = bf16(dinv[m] * (A[m,:] @ W)), A bf16, W pre-split ----
// CTA tile 64x128, 8 warps (2x4 grid, warp tile 32x32); XOR-swizzled smem:
//   A 16KB, W hi/lo 32KB each = 80KB -> 2 CTAs/SM   (identical to R11)
#define SA     0
#define SW_HI  16384
#define SW_LO  49152
#define SM_TOTAL 81920

__global__ __launch_bounds__(256, 2) void k_gemm_mma(const __nv_bfloat16* __restrict__ A,
                                                     const unsigned char* __restrict__ Whi,
                                                     const unsigned char* __restrict__ Wlo,
                                                     __nv_bfloat16* __restrict__ C, int nrows) {
    extern __shared__ char smem[];
    uint32_t sb = smem_u32(smem);
    int tid = threadIdx.x, lane = tid & 31, wid = tid >> 5;
    int wm = wid >> 2, wn = wid & 3;      // 2x4 warp grid; warp tile 32x32
    int m0 = blockIdx.x * 64;

    // prologue W: straight byte copy of pre-split, pre-swizzled images
    {
        const uint4* __restrict__ s1 = (const uint4*)Whi;
        const uint4* __restrict__ s2 = (const uint4*)Wlo;
        uint4* d1 = (uint4*)(smem + SW_HI);
        uint4* d2 = (uint4*)(smem + SW_LO);
#pragma unroll
        for (int j = 0; j < 8; ++j) {
            int i = j * 256 + tid;
            d1[i] = s1[i];
            d2[i] = s2[i];
        }
    }
    // prologue A: 64 rows x 256B bf16, straight copy with swizzle
#pragma unroll
    for (int j = 0; j < 4; ++j) {
        int idx = j * 256 + tid;          // 1024 items: r*16 + chunk
        int r = idx >> 4, c = idx & 15;
        int m = m0 + r;
        uint4 v = make_uint4(0u, 0u, 0u, 0u);
        if (m < nrows) v = *(const uint4*)&A[(size_t)m * H + c * 8];
        *(uint4*)(smem + SA + SWZ(r * 256 + c * 16)) = v;
    }
    __syncthreads();

    float c[2][4][4];
#pragma unroll
    for (int mi = 0; mi < 2; ++mi)
#pragma unroll
        for (int nj = 0; nj < 4; ++nj)
#pragma unroll
            for (int q = 0; q < 4; ++q) c[mi][nj][q] = 0.f;

    int arow_lo = lane & 15;
    int asel = lane >> 4;

#pragma unroll
    for (int kc = 0; kc < 8; ++kc) {
        uint32_t a[2][4], bhi[2][4], blo[2][4];
#pragma unroll
        for (int mi = 0; mi < 2; ++mi) {
            int row = wm * 32 + mi * 16 + arow_lo;
            LDSM_X4(a[mi], sb + SA + SWZ(row * 256 + (kc * 2 + asel) * 16));
        }
#pragma unroll
        for (int ni = 0; ni < 2; ++ni) {
            int krow = kc * 16 + arow_lo;
            uint32_t off = SWZ(krow * 256 + (wn * 4 + ni * 2 + asel) * 16);
            LDSM_X4_T(bhi[ni], sb + SW_HI + off);
            LDSM_X4_T(blo[ni], sb + SW_LO + off);
        }
        // product 1: A x Whi
#pragma unroll
        for (int mi = 0; mi < 2; ++mi)
#pragma unroll
            for (int ni = 0; ni < 2; ++ni) {
                MMA_BF16(c[mi][2 * ni],     a[mi], bhi[ni][0], bhi[ni][1]);
                MMA_BF16(c[mi][2 * ni + 1], a[mi], bhi[ni][2], bhi[ni][3]);
            }
        // product 2: A x Wlo
#pragma unroll
        for (int mi = 0; mi < 2; ++mi)
#pragma unroll
            for (int ni = 0; ni < 2; ++ni) {
                MMA_BF16(c[mi][2 * ni],     a[mi], blo[ni][0], blo[ni][1]);
                MMA_BF16(c[mi][2 * ni + 1], a[mi], blo[ni][2], blo[ni][3]);
            }
    }

    // epilogue: scale by dinv (inline rsqrt of degree), store bf16
#pragma unroll
    for (int mi = 0; mi < 2; ++mi) {
        int r = m0 + wm * 32 + mi * 16 + (lane >> 2);
        int r8 = r + 8;
        float d0 = (r < nrows) ? rsqrtf((float)(g_count[r] + 1)) : 0.f;
        float d8 = (r8 < nrows) ? rsqrtf((float)(g_count[r8] + 1)) : 0.f;
#pragma unroll
        for (int nj = 0; nj < 4; ++nj) {
            int col = wn * 32 + nj * 8 + (lane & 3) * 2;
            if (r < nrows)
                *(uint32_t*)&C[(size_t)r * H + col] = pack2(d0 * c[mi][nj][0], d0 * c[mi][nj][1]);
            if (r8 < nrows)
                *(uint32_t*)&C[(size_t)r8 * H + col] = pack2(d8 * c[mi][nj][2], d8 * c[mi][nj][3]);
        }
    }
}

// ---- SpMM: h[i] = bf16(relu(dinv[i]*(t[i] + sum_src t[src]) + b)), t bf16 ----
// 1 warp per node; lane covers 4 cols (uint2 = 4 bf16)   [exact R8/R11 version]
__global__ __launch_bounds__(256) void k_spmm(const __nv_bfloat16* __restrict__ t,
                                              const float* __restrict__ bias,
                                              __nv_bfloat16* __restrict__ h, int n) {
    int node = (blockIdx.x * blockDim.x + threadIdx.x) >> 5;
    if (node >= n) return;
    int lane = threadIdx.x & 31;
    const uint2* __restrict__ t2 = (const uint2*)t;   // row = 32 uint2

    float di = g_dinv[node];
    int e0 = g_rowptr[node], e1 = g_rowptr[node + 1];
    uint2 sv = t2[(size_t)node * 32 + lane];
    float2 s0 = b2f(sv.x), s1 = b2f(sv.y);
    float ax = s0.x, ay = s0.y, az = s1.x, aw = s1.y;
    float bx = 0.f, by = 0.f, bz = 0.f, bw = 0.f;
    float cx = 0.f, cy = 0.f, cz = 0.f, cw = 0.f;
    float dx = 0.f, dy = 0.f, dz = 0.f, dw = 0.f;
    int e = e0;
    for (; e + 3 < e1; e += 4) {
        int i0 = g_src[e], i1 = g_src[e + 1], i2 = g_src[e + 2], i3 = g_src[e + 3];
        uint2 v0 = t2[(size_t)i0 * 32 + lane];
        uint2 v1 = t2[(size_t)i1 * 32 + lane];
        uint2 v2 = t2[(size_t)i2 * 32 + lane];
        uint2 v3 = t2[(size_t)i3 * 32 + lane];
        float2 p;
        p = b2f(v0.x); ax += p.x; ay += p.y;  p = b2f(v0.y); az += p.x; aw += p.y;
        p = b2f(v1.x); bx += p.x; by += p.y;  p = b2f(v1.y); bz += p.x; bw += p.y;
        p = b2f(v2.x); cx += p.x; cy += p.y;  p = b2f(v2.y); cz += p.x; cw += p.y;
        p = b2f(v3.x); dx += p.x; dy += p.y;  p = b2f(v3.y); dz += p.x; dw += p.y;
    }
    for (; e < e1; ++e) {
        int s = g_src[e];
        uint2 v = t2[(size_t)s * 32 + lane];
        float2 p;
        p = b2f(v.x); ax += p.x; ay += p.y;
        p = b2f(v.y); az += p.x; aw += p.y;
    }
    float4 bi = ((const float4*)bias)[lane];
    float r0 = fmaxf(fmaf(di, (ax + bx) + (cx + dx), bi.x), 0.f);
    float r1 = fmaxf(fmaf(di, (ay + by) + (cy + dy), bi.y), 0.f);
    float r2 = fmaxf(fmaf(di, (az + bz) + (cz + dz), bi.z), 0.f);
    float r3 = fmaxf(fmaf(di, (aw + bw) + (cw + dw), bi.w), 0.f);
    uint2 o;
    o.x = pack2(r0, r1);
    o.y = pack2(r2, r3);
    ((uint2*)h)[(size_t)node * 32 + lane] = o;
}

// ---- global mean pool (h bf16): 4 sub-blocks per graph accumulate raw sums ----
__global__ void k_pool(const __nv_bfloat16* __restrict__ h, int off) {
    int g = blockIdx.x, part = blockIdx.y, tx = threadIdx.x;
    int s = g_gptr[g], e = g_gptr[g + 1];
    float sum = 0.f;
    for (int i = s + part; i < e; i += 4)
        sum += __bfloat162float(h[(size_t)i * H + tx]);
    atomicAdd(&g_p[g * (5 * H) + off + tx], sum);
}

// ---- MLP head (normalizes pooled sums by graph size) ----
__global__ void k_mlp1(const float* __restrict__ Wl1, const float* __restrict__ bl1) {
    __shared__ float ps[5 * H];
    int g = blockIdx.y;
    int s = g_gptr[g], e = g_gptr[g + 1];
    float inv = 1.f / (float)((e - s) > 0 ? (e - s) : 1);
    int j = blockIdx.x * H + threadIdx.x;
    for (int k = threadIdx.x; k < 5 * H; k += H) ps[k] = g_p[g * (5 * H) + k] * inv;
    __syncthreads();
    float acc = bl1[j];
    for (int k = 0; k < 5 * H; ++k) acc = fmaf(ps[k], Wl1[(size_t)k * (5 * H) + j], acc);
    g_q[g * (5 * H) + j] = fmaxf(acc, 0.f);
}

__global__ void k_mlp2(const float* __restrict__ Wl2, const float* __restrict__ bl2,
                       float* __restrict__ out) {
    __shared__ float red[H];
    int g = blockIdx.x, tid = threadIdx.x;
    float s = 0.f;
    for (int k = tid; k < 5 * H; k += H) s = fmaf(g_q[g * (5 * H) + k], Wl2[k], s);
    red[tid] = s;
    __syncthreads();
    for (int d = H / 2; d > 0; d >>= 1) {
        if (tid < d) red[tid] += red[tid + d];
        __syncthreads();
    }
    if (tid == 0) out[g] = red[0] + bl2[0];
}

// ---- launch ----
extern "C" void kernel_launch(void* const* d_in, const int* in_sizes, int n_in,
                              void* d_out, int out_size) {
    const float* x     = (const float*)d_in[0];
    const int*   edge  = (const int*)d_in[1];
    const int*   batch = (const int*)d_in[2];
    const float* B[5]  = {(const float*)d_in[4], (const float*)d_in[6],
                          (const float*)d_in[8], (const float*)d_in[10],
                          (const float*)d_in[10]};  // layer 5 reuses b4
    const float* Wl1 = (const float*)d_in[11];
    const float* bl1 = (const float*)d_in[12];
    const float* Wl2 = (const float*)d_in[13];
    const float* bl2 = (const float*)d_in[14];
    float* out = (float*)d_out;

    int n = in_sizes[0] / H;
    int E = in_sizes[1] / 2;
    const int* row = edge;       // sources
    const int* col = edge + E;   // targets

    __nv_bfloat16 *hA, *hB, *tbuf;
    cudaGetSymbolAddress((void**)&hA, g_hA);
    cudaGetSymbolAddress((void**)&hB, g_hB);
    cudaGetSymbolAddress((void**)&tbuf, g_t);
    unsigned char *whi, *wlo;
    cudaGetSymbolAddress((void**)&whi, g_whi);
    cudaGetSymbolAddress((void**)&wlo, g_wlo);

    cudaFuncSetAttribute(k_gemm_mma, cudaFuncAttributeMaxDynamicSharedMemorySize, SM_TOTAL);

    const int TB = 256;
    int nbScan = (n + SCANB - 1) / SCANB;
    int tiles = (n + 63) / 64;
    int cvtN = n * 32;           // float4 chunks of x

    // first GEMM kept at launch index 3 (the launch ncu -s 5 -c 1 captures)
    k_wprep<<<dim3(8, 4), 256>>>((const float*)d_in[3], (const float*)d_in[5],
                                 (const float*)d_in[7], (const float*)d_in[9]);  // 0
    k_init_cvt<<<(cvtN + TB - 1) / TB, TB>>>(x, hA, n);             // 1 (cvt x, zero g_p)
    k_hist_gmin<<<(E + TB - 1) / TB, TB>>>(col, batch, E, n);       // 2 (hist + gmin)
    k_gemm_mma<<<tiles, 256, SM_TOTAL>>>(hA, whi, wlo, tbuf, n);    // 3  <- profiled
    k_scan1<<<nbScan, SCANB>>>(n);                                  // 4 (+ dinv)
    k_scan2<<<1, 128>>>(nbScan, n);                                 // 5
    k_scan3<<<nbScan, SCANB>>>(n);                                  // 6
    k_scatter<<<(E + TB - 1) / TB, TB>>>(row, col, E);              // 7
    k_gfix<<<1, NG>>>();                                            // 8

    __nv_bfloat16* bufs[2] = {hB, hA};   // layer l output buffer = bufs[l & 1]
    // layer 1 tail
    k_spmm<<<(n + 7) / 8, 256>>>(tbuf, B[0], bufs[0], n);
    k_pool<<<dim3(NG, 4), H>>>(bufs[0], 0);
    const __nv_bfloat16* hin = bufs[0];
    for (int l = 1; l < 5; ++l) {
        __nv_bfloat16* hout = bufs[l & 1];
        int widx = (l < 4) ? l : 3;      // layer 5 reuses W4
        k_gemm_mma<<<tiles, 256, SM_TOTAL>>>(hin, whi + (size_t)widx * 32768,
                                             wlo + (size_t)widx * 32768, tbuf, n);
        k_spmm<<<(n + 7) / 8, 256>>>(tbuf, B[l], hout, n);
        k_pool<<<dim3(NG, 4), H>>>(hout, l * H);
        hin = hout;
    }
    k_mlp1<<<dim3(5, NG), H>>>(Wl1, bl1);
    k_mlp2<<<NG, H>>>(Wl2, bl2, out);
}